// round 2
// baseline (speedup 1.0000x reference)
#include <cuda_runtime.h>
#include <cstdint>

// Problem constants
#define BB 32
#define NN 512
#define HH 128
constexpr float LN_EPS = 1e-5f;

// Scratch for h = silu(layernorm(s@W1^T + b1)) : (B, N, H) fp32, 8 MB
__device__ float g_h[(size_t)BB * NN * HH];

// ---------------------------------------------------------------------------
// tf32 helpers
// ---------------------------------------------------------------------------
__device__ __forceinline__ uint32_t f2tf32(float x) {
    uint32_t r;
    asm("cvt.rna.tf32.f32 %0, %1;" : "=r"(r) : "f"(x));
    return r;
}

__device__ __forceinline__ void mma_tf32(float* d, const uint32_t* a, const uint32_t* b) {
    asm volatile(
        "mma.sync.aligned.m16n8k8.row.col.f32.tf32.tf32.f32 "
        "{%0,%1,%2,%3}, {%4,%5,%6,%7}, {%8,%9}, {%0,%1,%2,%3};\n"
        : "+f"(d[0]), "+f"(d[1]), "+f"(d[2]), "+f"(d[3])
        : "r"(a[0]), "r"(a[1]), "r"(a[2]), "r"(a[3]),
          "r"(b[0]), "r"(b[1]));
}

// ---------------------------------------------------------------------------
// Stage 1: h = silu(layernorm(s @ W1^T + b1))
// Grid: 256 blocks x 256 threads. Each block: 64 rows of (B*N) x H=128.
// GEMM via tf32 mma, then LN+SiLU on the 64x128 tile in smem.
// ---------------------------------------------------------------------------
__global__ __launch_bounds__(256) void lin1_ln_silu_kernel(
    const float* __restrict__ s, const float* __restrict__ W1,
    const float* __restrict__ b1)
{
    // Union buffer: phase A = As[64][36] + Bs[128][36] (6912 floats),
    //               phase B = Hs[64][132] (8448 floats)
    __shared__ float smem[8448];
    float* As = smem;             // [64][36], row-major (m, k)
    float* Bs = smem + 64 * 36;   // [128][36], n-major: Bs[n][k] = W1[n][k]
    float* Hs = smem;             // [64][132]

    const int tid  = threadIdx.x;
    const int r0   = blockIdx.x * 64;
    const int w    = tid >> 5;
    const int lane = tid & 31;
    const int g    = lane >> 2;   // groupID
    const int tg   = lane & 3;    // thread-in-group
    const int wm   = w & 1;       // 2 warp-rows (32 M each)
    const int wn   = w >> 1;      // 4 warp-cols (32 N each)

    float acc[2][4][4];
    #pragma unroll
    for (int i = 0; i < 2; i++)
        #pragma unroll
        for (int j = 0; j < 4; j++)
            #pragma unroll
            for (int k = 0; k < 4; k++) acc[i][j][k] = 0.f;

    const uint32_t* A32 = (const uint32_t*)As;
    const uint32_t* B32 = (const uint32_t*)Bs;

    for (int kc = 0; kc < 4; kc++) {
        const int k0 = kc * 32;
        __syncthreads();
        // load s tile: 64 x 32 -> As (tf32). 512 float4 over 256 threads.
        #pragma unroll
        for (int it = 0; it < 2; it++) {
            int idx = tid + it * 256;
            int row = idx >> 3, q = idx & 7;
            float4 v = *(const float4*)(s + (size_t)(r0 + row) * HH + k0 + q * 4);
            uint32_t* dst = (uint32_t*)(As + row * 36 + q * 4);
            dst[0] = f2tf32(v.x); dst[1] = f2tf32(v.y);
            dst[2] = f2tf32(v.z); dst[3] = f2tf32(v.w);
        }
        // load W1 chunk: 128 rows (n) x 32 (k) -> Bs[n][k]. Natural row reads.
        #pragma unroll
        for (int it = 0; it < 4; it++) {
            int idx = tid + it * 256;
            int n = idx >> 3, q = idx & 7;
            float4 v = *(const float4*)(W1 + (size_t)n * HH + k0 + q * 4);
            uint32_t* dst = (uint32_t*)(Bs + n * 36 + q * 4);
            dst[0] = f2tf32(v.x); dst[1] = f2tf32(v.y);
            dst[2] = f2tf32(v.z); dst[3] = f2tf32(v.w);
        }
        __syncthreads();
        #pragma unroll
        for (int ks = 0; ks < 4; ks++) {
            const int kk = ks * 8;
            uint32_t af[2][4], bf[4][2];
            #pragma unroll
            for (int mt = 0; mt < 2; mt++) {
                int rm = wm * 32 + mt * 16;
                af[mt][0] = A32[(rm + g) * 36 + kk + tg];
                af[mt][1] = A32[(rm + g + 8) * 36 + kk + tg];
                af[mt][2] = A32[(rm + g) * 36 + kk + tg + 4];
                af[mt][3] = A32[(rm + g + 8) * 36 + kk + tg + 4];
            }
            #pragma unroll
            for (int nt = 0; nt < 4; nt++) {
                int cn = wn * 32 + nt * 8 + g;
                bf[nt][0] = B32[cn * 36 + kk + tg];
                bf[nt][1] = B32[cn * 36 + kk + tg + 4];
            }
            #pragma unroll
            for (int mt = 0; mt < 2; mt++)
                #pragma unroll
                for (int nt = 0; nt < 4; nt++)
                    mma_tf32(acc[mt][nt], af[mt], bf[nt]);
        }
    }

    __syncthreads();
    // Dump accumulators to Hs[64][132]
    #pragma unroll
    for (int mt = 0; mt < 2; mt++) {
        #pragma unroll
        for (int nt = 0; nt < 4; nt++) {
            int rm = wm * 32 + mt * 16 + g;
            int cn = wn * 32 + nt * 8 + 2 * tg;
            Hs[rm * 132 + cn]       = acc[mt][nt][0];
            Hs[rm * 132 + cn + 1]   = acc[mt][nt][1];
            Hs[(rm + 8) * 132 + cn]     = acc[mt][nt][2];
            Hs[(rm + 8) * 132 + cn + 1] = acc[mt][nt][3];
        }
    }
    __syncthreads();

    // LayerNorm (no affine) + SiLU, 8 rows per warp
    #pragma unroll
    for (int rr = 0; rr < 8; rr++) {
        int row = w * 8 + rr;
        float x[4];
        float sum = 0.f, sq = 0.f;
        #pragma unroll
        for (int k = 0; k < 4; k++) {
            float v = Hs[row * 132 + lane + 32 * k] + __ldg(b1 + lane + 32 * k);
            x[k] = v; sum += v; sq += v * v;
        }
        #pragma unroll
        for (int o = 16; o > 0; o >>= 1) {
            sum += __shfl_xor_sync(0xffffffffu, sum, o);
            sq  += __shfl_xor_sync(0xffffffffu, sq, o);
        }
        float mu  = sum * (1.f / 128.f);
        float var = sq * (1.f / 128.f) - mu * mu;
        float inv = rsqrtf(var + LN_EPS);
        #pragma unroll
        for (int k = 0; k < 4; k++) {
            float yv = (x[k] - mu) * inv;
            float sv = yv / (1.f + __expf(-yv));   // silu
            g_h[(size_t)(r0 + row) * HH + lane + 32 * k] = sv;
        }
    }
}

// ---------------------------------------------------------------------------
// Stage 2: v[b,i,c,d] = sum_j mask[b,i,j]*ev[b,i,j,c]*h[b,j,d]
// Per batch b: GEMM with M = (i,c) = 96 per block-tile (32 i x 3 c),
// K = j = 512 (16 tiles of 32), N = d = 128.
// Grid: (16 i-tiles, 32 batches) x 256 threads.
// ---------------------------------------------------------------------------
__global__ __launch_bounds__(256) void cfconv_kernel(
    const float* __restrict__ ev, const float* __restrict__ mask,
    float* __restrict__ out)
{
    __shared__ float As[96 * 36];   // A[m=i*3+c][k=j], tf32 bits
    __shared__ float Bs[32 * 136];  // B[k=j][n=d],    tf32 bits
    __shared__ float Ms[32 * 33];   // mask tile [i][j]

    const int tid  = threadIdx.x;
    const int b    = blockIdx.y;
    const int i0   = blockIdx.x * 32;
    const int w    = tid >> 5;
    const int lane = tid & 31;
    const int g    = lane >> 2;
    const int tg   = lane & 3;
    const int wm   = w & 1;     // 2 warp-rows (48 M each)
    const int wn   = w >> 1;    // 4 warp-cols (32 N each)

    float acc[3][4][4];
    #pragma unroll
    for (int i = 0; i < 3; i++)
        #pragma unroll
        for (int j = 0; j < 4; j++)
            #pragma unroll
            for (int k = 0; k < 4; k++) acc[i][j][k] = 0.f;

    const uint32_t* A32c = (const uint32_t*)As;
    const uint32_t* B32c = (const uint32_t*)Bs;

    for (int jt = 0; jt < 16; jt++) {
        const int j0 = jt * 32;
        __syncthreads();
        // mask tile 32x32 (256 float4, 1 per thread)
        {
            int row = tid >> 3, q = tid & 7;
            float4 v = *(const float4*)(mask + ((size_t)(b * NN + i0 + row)) * NN + j0 + q * 4);
            float* dst = Ms + row * 33 + q * 4;
            dst[0] = v.x; dst[1] = v.y; dst[2] = v.z; dst[3] = v.w;
        }
        // h tile 32x128 -> Bs[k][n] (tf32). 1024 float4.
        #pragma unroll
        for (int it = 0; it < 4; it++) {
            int idx = tid + it * 256;
            int row = idx >> 5, q = idx & 31;
            float4 v = *(const float4*)(g_h + ((size_t)(b * NN + j0 + row)) * HH + q * 4);
            uint32_t* dst = (uint32_t*)(Bs + row * 136 + q * 4);
            dst[0] = f2tf32(v.x); dst[1] = f2tf32(v.y);
            dst[2] = f2tf32(v.z); dst[3] = f2tf32(v.w);
        }
        __syncthreads();
        // ev tile 32 x (32 j x 3 c) -> A[m=i*3+c][j] = ev*mask (tf32). 768 float4.
        #pragma unroll
        for (int it = 0; it < 3; it++) {
            int idx = tid + it * 256;      // 0..767
            int row = idx / 24;            // i_local
            int q   = idx - row * 24;      // float4 within the 96-float (j,c) row
            float4 v = *(const float4*)(ev + (((size_t)(b * NN + i0 + row)) * NN + j0) * 3 + q * 4);
            float fv[4] = {v.x, v.y, v.z, v.w};
            uint32_t* A32 = (uint32_t*)As;
            #pragma unroll
            for (int e = 0; e < 4; e++) {
                int jc = q * 4 + e;
                int j  = jc / 3;
                int c  = jc - 3 * j;
                float val = fv[e] * Ms[row * 33 + j];
                A32[(row * 3 + c) * 36 + j] = f2tf32(val);
            }
        }
        __syncthreads();
        // 4 k-steps of 8
        #pragma unroll
        for (int ks = 0; ks < 4; ks++) {
            const int kk = ks * 8;
            uint32_t af[3][4], bf[4][2];
            #pragma unroll
            for (int mt = 0; mt < 3; mt++) {
                int rm = wm * 48 + mt * 16;
                af[mt][0] = A32c[(rm + g) * 36 + kk + tg];
                af[mt][1] = A32c[(rm + g + 8) * 36 + kk + tg];
                af[mt][2] = A32c[(rm + g) * 36 + kk + tg + 4];
                af[mt][3] = A32c[(rm + g + 8) * 36 + kk + tg + 4];
            }
            #pragma unroll
            for (int nt = 0; nt < 4; nt++) {
                int cn = wn * 32 + nt * 8 + g;
                bf[nt][0] = B32c[(kk + tg) * 136 + cn];
                bf[nt][1] = B32c[(kk + tg + 4) * 136 + cn];
            }
            #pragma unroll
            for (int mt = 0; mt < 3; mt++)
                #pragma unroll
                for (int nt = 0; nt < 4; nt++)
                    mma_tf32(acc[mt][nt], af[mt], bf[nt]);
        }
    }

    // Write out: out[((b*N + i)*3 + c)*H + d] = out[((b*N+i0)*3 + m)*H + d]
    const size_t obase = ((size_t)(b * NN + i0)) * 3 * HH;
    #pragma unroll
    for (int mt = 0; mt < 3; mt++) {
        #pragma unroll
        for (int nt = 0; nt < 4; nt++) {
            int m  = wm * 48 + mt * 16 + g;
            int cn = wn * 32 + nt * 8 + 2 * tg;
            float2 v0 = make_float2(acc[mt][nt][0], acc[mt][nt][1]);
            float2 v1 = make_float2(acc[mt][nt][2], acc[mt][nt][3]);
            *(float2*)(out + obase + (size_t)m * HH + cn)       = v0;
            *(float2*)(out + obase + (size_t)(m + 8) * HH + cn) = v1;
        }
    }
}

// ---------------------------------------------------------------------------
// Launch
// ---------------------------------------------------------------------------
extern "C" void kernel_launch(void* const* d_in, const int* in_sizes, int n_in,
                              void* d_out, int out_size) {
    (void)in_sizes; (void)n_in; (void)out_size;
    const float* s    = (const float*)d_in[0];
    const float* ev   = (const float*)d_in[1];
    const float* mask = (const float*)d_in[2];
    const float* W1   = (const float*)d_in[3];
    const float* b1   = (const float*)d_in[4];
    float* out = (float*)d_out;

    lin1_ln_silu_kernel<<<256, 256>>>(s, W1, b1);
    cfconv_kernel<<<dim3(16, 32), 256>>>(ev, mask, out);
}